// round 9
// baseline (speedup 1.0000x reference)
#include <cuda_runtime.h>

// ---------------------------------------------------------------------------
// MPS_RNN_2D forward.  L=M=8, S=2, D=32.
// lane = bond index d; WELE=8 elements per warp; hidden lattice state in
// warp-private shared memory sHV[k][col][d] ONLY (left input is read from
// the previous scan site's column; h_left==1 at j==0 is folded into v).
// Matrices repacked into [site][b4][comp][d] float4 over b; matvec via
// fma.rn.f32x2.  Epilogue: warp-wide 32x32 multireduce (31 SHFL for all 4
// dot products of all 8 elements), results one per lane (lane 4k+q).
// ---------------------------------------------------------------------------

#define NQ    64
#define EPSF  1e-10f
#define TPB   128
#define WELE  8
#define EPB   32            // (TPB/32) * WELE

// [site][b4(8)][comp(4)][d(32)]: comp 0=Mh(s0),1=Mh(s1),2=Mv(s0),3=Mv(s1)
__device__ float4 g2[64 * 1024];          // 1 MB
__device__ float4 g_vecp[64 * 32];        // [site][d] = {v0_eff, v1_eff, eta^2, w}
__device__ float  g_c[64];

#define FFMA2(acc, m, h) \
    asm("fma.rn.f32x2 %0, %1, %2, %0;" : "+l"(acc) : "l"(m), "l"(h))
#define UNPACK2(lo, hi, p) \
    asm("mov.b64 {%0, %1}, %2;" : "=f"(lo), "=f"(hi) : "l"(p))

// ---------------------------------------------------------------------------
__global__ void repack_kernel(const float* __restrict__ Mh,
                              const float* __restrict__ Mv,
                              const float* __restrict__ v,
                              const float* __restrict__ w,
                              const float* __restrict__ c,
                              const float* __restrict__ eta) {
    int site = blockIdx.x;                // scan order
    int row  = site >> 3;
    int j    = site & 7;
    int col  = (row & 1) ? (7 - j) : j;   // snake
    int cell = row * 8 + col;

    int t    = threadIdx.x;               // 1024 threads
    int d    = t & 31;
    int idx  = t >> 5;
    int comp = idx & 3;
    int b4   = idx >> 2;

    const float* base = (comp < 2) ? Mh : Mv;
    const float* src  = base + (size_t)cell * 2048 + (size_t)(comp & 1) * 1024
                        + d * 32 + b4 * 4;
    g2[site * 1024 + (b4 * 4 + comp) * 32 + d] = *(const float4*)src;

    if (t < 32) {
        float v0 = v[cell * 64 + t];
        float v1 = v[cell * 64 + 32 + t];
        if (j == 0) {                      // fold Mh . ones (left boundary)
            const float* m0 = Mh + (size_t)cell * 2048 + t * 32;
            const float* m1 = m0 + 1024;
            #pragma unroll
            for (int b = 0; b < 32; ++b) { v0 += m0[b]; v1 += m1[b]; }
        }
        float e = eta[cell * 32 + t];
        float4 gv;
        gv.x = v0; gv.y = v1; gv.z = e * e; gv.w = w[cell * 32 + t];
        g_vecp[site * 32 + t] = gv;
        if (t == 0) g_c[site] = c[cell];
    }
}

// ---------------------------------------------------------------------------
// H: read left input from sHV[colprev] (prev scan site).  V: read vertical
// input from sHV[col] (prev row, not yet overwritten this row).
template <bool H, bool V>
__device__ __forceinline__ void site_body(
    const ulonglong2* __restrict__ gm,
    float* __restrict__ sHVw,              // [WELE][8][32] lattice state
    int lane, int col, int colprev,
    float4 gv, float rc, unsigned bits,
    float& la_mine, int& nc_mine)
{
    unsigned long long acc0[WELE], acc1[WELE];
    #pragma unroll
    for (int k = 0; k < WELE; ++k) { acc0[k] = 0ull; acc1[k] = 0ull; }

    if (H || V) {
        #pragma unroll
        for (int b4 = 0; b4 < 8; ++b4) {
            const ulonglong2* gb = gm + (b4 * 4) * 32 + lane;
            ulonglong2 m0, m1, m2, m3;
            if (H) { m0 = gb[0];  m1 = gb[32]; }
            if (V) { m2 = gb[64]; m3 = gb[96]; }
            #pragma unroll
            for (int k = 0; k < WELE; ++k) {
                if (H) {
                    ulonglong2 hl = *reinterpret_cast<const ulonglong2*>(
                        sHVw + (k * 8 + colprev) * 32 + b4 * 4);
                    FFMA2(acc0[k], m0.x, hl.x);  FFMA2(acc0[k], m0.y, hl.y);
                    FFMA2(acc1[k], m1.x, hl.x);  FFMA2(acc1[k], m1.y, hl.y);
                }
                if (V) {
                    ulonglong2 hv = *reinterpret_cast<const ulonglong2*>(
                        sHVw + (k * 8 + col) * 32 + b4 * 4);
                    FFMA2(acc0[k], m2.x, hv.x);  FFMA2(acc0[k], m2.y, hv.y);
                    FFMA2(acc1[k], m3.x, hv.x);  FFMA2(acc1[k], m3.y, hv.y);
                }
            }
        }
    }

    // 32 per-lane partials: cur[4k+0]=eta2*hsel^2, +1=eta2*hoth^2,
    // +2=hsel^2, +3=w*hsel.  Keep hsel for the normalized store.
    float cur[32], hsel_r[WELE];
    #pragma unroll
    for (int k = 0; k < WELE; ++k) {
        float e0, o0, e1, o1;
        UNPACK2(e0, o0, acc0[k]);
        UNPACK2(e1, o1, acc1[k]);
        float hc0 = e0 + o0 + gv.x;
        float hc1 = e1 + o1 + gv.y;
        bool  s    = (bits >> k) & 1u;
        float hsel = s ? hc1 : hc0;
        float hoth = s ? hc0 : hc1;
        hsel_r[k]  = hsel;
        float s2 = hsel * hsel;
        cur[4 * k + 0] = gv.z * s2;
        cur[4 * k + 1] = gv.z * hoth * hoth;
        cur[4 * k + 2] = s2;
        cur[4 * k + 3] = gv.w * hsel;
    }

    // Warp multireduce: 31 SHFL + 31 FADD.  Lane t = 4k+q holds total q of
    // element k afterwards.
    #pragma unroll
    for (int off = 16; off >= 1; off >>= 1) {
        bool hi = (lane & off) != 0;
        #pragma unroll
        for (int i = 0; i < off; ++i) {
            float a = cur[i], b = cur[i + off];
            float send = hi ? a : b;
            float keep = hi ? b : a;
            cur[i] = keep + __shfl_xor_sync(0xffffffffu, send, off);
        }
    }

    float S = cur[0];
    float P = __shfl_xor_sync(0xffffffffu, S, 1);   // pair partner
    int   q = lane & 3;

    // q==0: S=QS, P=QO -> dla.   q==2: S=NR -> inv (broadcast below).
    // q==3: S=AW, P=NR -> phase sign without divide.
    if (q == 0)
        la_mine += 0.5f * (__logf(S + EPSF) - __logf(S + P + EPSF));
    if (q == 3)
        nc_mine += ((S + rc * (sqrtf(P) + EPSF)) < 0.0f) ? 1 : 0;
    float inv = __fdividef(1.0f, sqrtf(S) + EPSF);  // valid at q==2

    // Normalize + store to lattice column: inv for element k is at lane 4k+2.
    #pragma unroll
    for (int k = 0; k < WELE; ++k) {
        float ik = __shfl_sync(0xffffffffu, inv, 4 * k + 2);
        sHVw[(k * 8 + col) * 32 + lane] = hsel_r[k] * ik;
    }
}

// ---------------------------------------------------------------------------
__global__ void __launch_bounds__(TPB, 5)
mps_main_kernel(const int* __restrict__ x, float* __restrict__ out, int B)
{
    extern __shared__ float smem[];
    const int lane = threadIdx.x & 31;
    const int wid  = threadIdx.x >> 5;
    const int ebl  = wid * WELE;
    float* sHVw = smem + ebl * 8 * 32;              // [WELE][8][32]
    const long eg0 = (long)blockIdx.x * EPB + ebl;

    // 64-bit occupation mask; lane k keeps element k's mask.
    unsigned long long msk = 0ull;
    #pragma unroll
    for (int k = 0; k < WELE; ++k) {
        long e = eg0 + k;
        int v0 = 0, v1 = 0;
        if (e < B) {
            v0 = x[e * NQ + lane];
            v1 = x[e * NQ + 32 + lane];
        }
        unsigned lo = __ballot_sync(0xffffffffu, v0 != 0);
        unsigned hi = __ballot_sync(0xffffffffu, v1 != 0);
        if (lane == k) msk = (unsigned long long)lo
                           | ((unsigned long long)hi << 32);
    }

    float la_mine = 0.0f;    // valid at lanes 4k+0 (element k)
    int   nc_mine = 0;       // valid at lanes 4k+3 (element k)

    #pragma unroll 1
    for (int row = 0; row < 8; ++row) {
        #pragma unroll 1
        for (int j = 0; j < 8; ++j) {
            const int site    = row * 8 + j;
            const int col     = (row & 1) ? (7 - j) : j;
            const int colprev = (row & 1) ? (8 - j) : (j - 1);  // j>0 only

            const float4 gv = g_vecp[site * 32 + lane];
            const float  rc = g_c[site];
            const ulonglong2* gm =
                reinterpret_cast<const ulonglong2*>(g2) + site * 1024;

            unsigned bits = __ballot_sync(
                0xffffffffu, (lane < WELE) && (unsigned)(msk & 1ull));
            msk >>= 1;

            if (row == 0) {
                if (j == 0)
                    site_body<false, false>(gm, sHVw, lane, col, colprev,
                                            gv, rc, bits, la_mine, nc_mine);
                else
                    site_body<true, false>(gm, sHVw, lane, col, colprev,
                                           gv, rc, bits, la_mine, nc_mine);
            } else {
                if (j == 0)
                    site_body<false, true>(gm, sHVw, lane, col, colprev,
                                           gv, rc, bits, la_mine, nc_mine);
                else
                    site_body<true, true>(gm, sHVw, lane, col, colprev,
                                          gv, rc, bits, la_mine, nc_mine);
            }
            __syncwarp();
        }
    }

    {
        int k = lane >> 2;
        long e = eg0 + k;
        if (e < B) {
            if ((lane & 3) == 0) out[e * 2 + 0] = la_mine;
            if ((lane & 3) == 3) out[e * 2 + 1] =
                3.14159274101257324f * (float)nc_mine;
        }
    }
}

// ---------------------------------------------------------------------------
extern "C" void kernel_launch(void* const* d_in, const int* in_sizes, int n_in,
                              void* d_out, int out_size) {
    const int*   x   = (const int*)  d_in[0];
    const float* Mh  = (const float*)d_in[1];
    const float* Mv  = (const float*)d_in[2];
    const float* v   = (const float*)d_in[3];
    const float* w   = (const float*)d_in[4];
    const float* c   = (const float*)d_in[5];
    const float* eta = (const float*)d_in[6];
    float* out = (float*)d_out;

    int B = in_sizes[0] / NQ;

    repack_kernel<<<64, 1024>>>(Mh, Mv, v, w, c, eta);

    const size_t smem_bytes = (size_t)(EPB * 8 * 32) * sizeof(float);
    cudaFuncSetAttribute(mps_main_kernel,
                         cudaFuncAttributeMaxDynamicSharedMemorySize,
                         (int)smem_bytes);

    int grid = (B + EPB - 1) / EPB;
    mps_main_kernel<<<grid, TPB, smem_bytes>>>(x, out, B);
}

// round 10
// speedup vs baseline: 1.0237x; 1.0237x over previous
#include <cuda_runtime.h>

// ---------------------------------------------------------------------------
// MPS_RNN_2D forward.  L=M=8, S=2, D=32.
// lane = bond index d; WELE=8 elements per warp; hidden lattice state in
// warp-private shared memory sHV[k][col][d] ONLY (left input read from the
// previous scan site's column; h_left==1 at j==0 folded into v at repack).
// Matrices repacked into [site][b4][comp][d] float4 over b; matvec via
// fma.rn.f32x2.  Epilogue: warp-wide 32x32 multireduce (31 SHFL for all 4
// dot products of all 8 elements), results one per lane (lane 4k+q).
// ---------------------------------------------------------------------------

#define NQ    64
#define EPSF  1e-10f
#define TPB   128
#define WELE  8
#define EPB   32            // (TPB/32) * WELE

// [site][b4(8)][comp(4)][d(32)]: comp 0=Mh(s0),1=Mh(s1),2=Mv(s0),3=Mv(s1)
__device__ float4 g2[64 * 1024];          // 1 MB
__device__ float4 g_vecp[64 * 32];        // [site][d] = {v0_eff, v1_eff, eta^2, w}
__device__ float  g_c[64];

#define FFMA2(acc, m, h) \
    asm("fma.rn.f32x2 %0, %1, %2, %0;" : "+l"(acc) : "l"(m), "l"(h))
#define UNPACK2(lo, hi, p) \
    asm("mov.b64 {%0, %1}, %2;" : "=f"(lo), "=f"(hi) : "l"(p))

// ---------------------------------------------------------------------------
__global__ void repack_kernel(const float* __restrict__ Mh,
                              const float* __restrict__ Mv,
                              const float* __restrict__ v,
                              const float* __restrict__ w,
                              const float* __restrict__ c,
                              const float* __restrict__ eta) {
    int site = blockIdx.x;                // scan order
    int row  = site >> 3;
    int j    = site & 7;
    int col  = (row & 1) ? (7 - j) : j;   // snake
    int cell = row * 8 + col;

    int t    = threadIdx.x;               // 1024 threads
    int d    = t & 31;
    int idx  = t >> 5;
    int comp = idx & 3;
    int b4   = idx >> 2;

    const float* base = (comp < 2) ? Mh : Mv;
    const float* src  = base + (size_t)cell * 2048 + (size_t)(comp & 1) * 1024
                        + d * 32 + b4 * 4;
    g2[site * 1024 + (b4 * 4 + comp) * 32 + d] = *(const float4*)src;

    if (t < 32) {
        float v0 = v[cell * 64 + t];
        float v1 = v[cell * 64 + 32 + t];
        if (j == 0) {                      // fold Mh . ones (left boundary)
            const float* m0 = Mh + (size_t)cell * 2048 + t * 32;
            const float* m1 = m0 + 1024;
            #pragma unroll
            for (int b = 0; b < 32; ++b) { v0 += m0[b]; v1 += m1[b]; }
        }
        float e = eta[cell * 32 + t];
        float4 gv;
        gv.x = v0; gv.y = v1; gv.z = e * e; gv.w = w[cell * 32 + t];
        g_vecp[site * 32 + t] = gv;
        if (t == 0) g_c[site] = c[cell];
    }
}

// ---------------------------------------------------------------------------
// H: read left input from sHV[colprev] (prev scan site).  V: read vertical
// input from sHV[col] (prev row, not yet overwritten this row).
template <bool H, bool V>
__device__ __forceinline__ void site_body(
    const ulonglong2* __restrict__ gm,
    float* __restrict__ sHVw,              // [WELE][8][32] lattice state
    int lane, int col, int colprev,
    float4 gv, float rc, unsigned bits,
    float& la_mine, int& nc_mine)
{
    unsigned long long acc0[WELE], acc1[WELE];
    #pragma unroll
    for (int k = 0; k < WELE; ++k) { acc0[k] = 0ull; acc1[k] = 0ull; }

    if (H || V) {
        #pragma unroll
        for (int b4 = 0; b4 < 8; ++b4) {
            const ulonglong2* gb = gm + (b4 * 4) * 32 + lane;
            ulonglong2 m0, m1, m2, m3;
            if (H) { m0 = gb[0];  m1 = gb[32]; }
            if (V) { m2 = gb[64]; m3 = gb[96]; }
            #pragma unroll
            for (int k = 0; k < WELE; ++k) {
                if (H) {
                    ulonglong2 hl = *reinterpret_cast<const ulonglong2*>(
                        sHVw + (k * 8 + colprev) * 32 + b4 * 4);
                    FFMA2(acc0[k], m0.x, hl.x);  FFMA2(acc0[k], m0.y, hl.y);
                    FFMA2(acc1[k], m1.x, hl.x);  FFMA2(acc1[k], m1.y, hl.y);
                }
                if (V) {
                    ulonglong2 hv = *reinterpret_cast<const ulonglong2*>(
                        sHVw + (k * 8 + col) * 32 + b4 * 4);
                    FFMA2(acc0[k], m2.x, hv.x);  FFMA2(acc0[k], m2.y, hv.y);
                    FFMA2(acc1[k], m3.x, hv.x);  FFMA2(acc1[k], m3.y, hv.y);
                }
            }
        }
    }

    // 32 per-lane partials: cur[4k+0]=eta2*hsel^2, +1=eta2*hoth^2,
    // +2=hsel^2, +3=w*hsel.  Keep hsel for the normalized store.
    float cur[32], hsel_r[WELE];
    #pragma unroll
    for (int k = 0; k < WELE; ++k) {
        float e0, o0, e1, o1;
        UNPACK2(e0, o0, acc0[k]);
        UNPACK2(e1, o1, acc1[k]);
        float hc0 = e0 + o0 + gv.x;
        float hc1 = e1 + o1 + gv.y;
        bool  s    = (bits >> k) & 1u;
        float hsel = s ? hc1 : hc0;
        float hoth = s ? hc0 : hc1;
        hsel_r[k]  = hsel;
        float s2 = hsel * hsel;
        cur[4 * k + 0] = gv.z * s2;
        cur[4 * k + 1] = gv.z * hoth * hoth;
        cur[4 * k + 2] = s2;
        cur[4 * k + 3] = gv.w * hsel;
    }

    // Warp multireduce: 31 SHFL + 31 FADD.  Lane t = 4k+q holds total q of
    // element k afterwards.
    #pragma unroll
    for (int off = 16; off >= 1; off >>= 1) {
        bool hi = (lane & off) != 0;
        #pragma unroll
        for (int i = 0; i < off; ++i) {
            float a = cur[i], b = cur[i + off];
            float send = hi ? a : b;
            float keep = hi ? b : a;
            cur[i] = keep + __shfl_xor_sync(0xffffffffu, send, off);
        }
    }

    float S = cur[0];
    float P = __shfl_xor_sync(0xffffffffu, S, 1);   // pair partner
    int   q = lane & 3;

    // q==0: S=QS, P=QO -> dla.   q==2: S=NR -> inv (broadcast below).
    // q==3: S=AW, P=NR -> phase sign without divide.
    if (q == 0)
        la_mine += 0.5f * (__logf(S + EPSF) - __logf(S + P + EPSF));
    if (q == 3)
        nc_mine += ((S + rc * (sqrtf(P) + EPSF)) < 0.0f) ? 1 : 0;
    float inv = __fdividef(1.0f, sqrtf(S) + EPSF);  // valid at q==2

    // Normalize + store to lattice column: inv for element k is at lane 4k+2.
    #pragma unroll
    for (int k = 0; k < WELE; ++k) {
        float ik = __shfl_sync(0xffffffffu, inv, 4 * k + 2);
        sHVw[(k * 8 + col) * 32 + lane] = hsel_r[k] * ik;
    }
}

// ---------------------------------------------------------------------------
__global__ void __launch_bounds__(TPB, 4)
mps_main_kernel(const int* __restrict__ x, float* __restrict__ out, int B)
{
    extern __shared__ float smem[];
    const int lane = threadIdx.x & 31;
    const int wid  = threadIdx.x >> 5;
    const int ebl  = wid * WELE;
    float* sHVw = smem + ebl * 8 * 32;              // [WELE][8][32]
    const long eg0 = (long)blockIdx.x * EPB + ebl;

    // 64-bit occupation mask; lane k keeps element k's mask.
    unsigned long long msk = 0ull;
    #pragma unroll
    for (int k = 0; k < WELE; ++k) {
        long e = eg0 + k;
        int v0 = 0, v1 = 0;
        if (e < B) {
            v0 = x[e * NQ + lane];
            v1 = x[e * NQ + 32 + lane];
        }
        unsigned lo = __ballot_sync(0xffffffffu, v0 != 0);
        unsigned hi = __ballot_sync(0xffffffffu, v1 != 0);
        if (lane == k) msk = (unsigned long long)lo
                           | ((unsigned long long)hi << 32);
    }

    float la_mine = 0.0f;    // valid at lanes 4k+0 (element k)
    int   nc_mine = 0;       // valid at lanes 4k+3 (element k)

    #pragma unroll 1
    for (int row = 0; row < 8; ++row) {
        #pragma unroll 1
        for (int j = 0; j < 8; ++j) {
            const int site    = row * 8 + j;
            const int col     = (row & 1) ? (7 - j) : j;
            const int colprev = (row & 1) ? (8 - j) : (j - 1);  // j>0 only

            const float4 gv = g_vecp[site * 32 + lane];
            const float  rc = g_c[site];
            const ulonglong2* gm =
                reinterpret_cast<const ulonglong2*>(g2) + site * 1024;

            unsigned bits = __ballot_sync(
                0xffffffffu, (lane < WELE) && (unsigned)(msk & 1ull));
            msk >>= 1;

            if (row == 0) {
                if (j == 0)
                    site_body<false, false>(gm, sHVw, lane, col, colprev,
                                            gv, rc, bits, la_mine, nc_mine);
                else
                    site_body<true, false>(gm, sHVw, lane, col, colprev,
                                           gv, rc, bits, la_mine, nc_mine);
            } else {
                if (j == 0)
                    site_body<false, true>(gm, sHVw, lane, col, colprev,
                                           gv, rc, bits, la_mine, nc_mine);
                else
                    site_body<true, true>(gm, sHVw, lane, col, colprev,
                                          gv, rc, bits, la_mine, nc_mine);
            }
            __syncwarp();
        }
    }

    {
        int k = lane >> 2;
        long e = eg0 + k;
        if (e < B) {
            if ((lane & 3) == 0) out[e * 2 + 0] = la_mine;
            if ((lane & 3) == 3) out[e * 2 + 1] =
                3.14159274101257324f * (float)nc_mine;
        }
    }
}

// ---------------------------------------------------------------------------
extern "C" void kernel_launch(void* const* d_in, const int* in_sizes, int n_in,
                              void* d_out, int out_size) {
    const int*   x   = (const int*)  d_in[0];
    const float* Mh  = (const float*)d_in[1];
    const float* Mv  = (const float*)d_in[2];
    const float* v   = (const float*)d_in[3];
    const float* w   = (const float*)d_in[4];
    const float* c   = (const float*)d_in[5];
    const float* eta = (const float*)d_in[6];
    float* out = (float*)d_out;

    int B = in_sizes[0] / NQ;

    repack_kernel<<<64, 1024>>>(Mh, Mv, v, w, c, eta);

    const size_t smem_bytes = (size_t)(EPB * 8 * 32) * sizeof(float);
    cudaFuncSetAttribute(mps_main_kernel,
                         cudaFuncAttributeMaxDynamicSharedMemorySize,
                         (int)smem_bytes);

    int grid = (B + EPB - 1) / EPB;
    mps_main_kernel<<<grid, TPB, smem_bytes>>>(x, out, B);
}

// round 11
// speedup vs baseline: 1.0252x; 1.0015x over previous
#include <cuda_runtime.h>

// ---------------------------------------------------------------------------
// MPS_RNN_2D forward.  L=M=8, S=2, D=32.
// lane = bond index d; WELE=8 elements per warp; hidden lattice state in
// warp-private shared memory sHV[k][col][d] ONLY (left input read from the
// previous scan site's column; h_left==1 at j==0 folded into v at repack).
// Matrices repacked into [site][b4][comp][d] float4 over b; matvec via
// fma.rn.f32x2.  Epilogue: warp-wide 32x32 multireduce (31 SHFL for all 4
// dot products of all 8 elements), results one per lane (lane 4k+q).
// ---------------------------------------------------------------------------

#define NQ    64
#define EPSF  1e-10f
#define TPB   128
#define WELE  8
#define EPB   32            // (TPB/32) * WELE

// [site][b4(8)][comp(4)][d(32)]: comp 0=Mh(s0),1=Mh(s1),2=Mv(s0),3=Mv(s1)
__device__ float4 g2[64 * 1024];          // 1 MB
__device__ float4 g_vecp[64 * 32];        // [site][d] = {v0_eff, v1_eff, eta^2, w}
__device__ float  g_c[64];

#define FFMA2(acc, m, h) \
    asm("fma.rn.f32x2 %0, %1, %2, %0;" : "+l"(acc) : "l"(m), "l"(h))
#define UNPACK2(lo, hi, p) \
    asm("mov.b64 {%0, %1}, %2;" : "=f"(lo), "=f"(hi) : "l"(p))

// ---------------------------------------------------------------------------
__global__ void repack_kernel(const float* __restrict__ Mh,
                              const float* __restrict__ Mv,
                              const float* __restrict__ v,
                              const float* __restrict__ w,
                              const float* __restrict__ c,
                              const float* __restrict__ eta) {
    int site = blockIdx.x;                // scan order
    int row  = site >> 3;
    int j    = site & 7;
    int col  = (row & 1) ? (7 - j) : j;   // snake
    int cell = row * 8 + col;

    int t    = threadIdx.x;               // 1024 threads
    int d    = t & 31;
    int idx  = t >> 5;
    int comp = idx & 3;
    int b4   = idx >> 2;

    const float* base = (comp < 2) ? Mh : Mv;
    const float* src  = base + (size_t)cell * 2048 + (size_t)(comp & 1) * 1024
                        + d * 32 + b4 * 4;
    g2[site * 1024 + (b4 * 4 + comp) * 32 + d] = *(const float4*)src;

    if (t < 32) {
        float v0 = v[cell * 64 + t];
        float v1 = v[cell * 64 + 32 + t];
        if (j == 0) {                      // fold Mh . ones (left boundary)
            const float* m0 = Mh + (size_t)cell * 2048 + t * 32;
            const float* m1 = m0 + 1024;
            #pragma unroll
            for (int b = 0; b < 32; ++b) { v0 += m0[b]; v1 += m1[b]; }
        }
        float e = eta[cell * 32 + t];
        float4 gv;
        gv.x = v0; gv.y = v1; gv.z = e * e; gv.w = w[cell * 32 + t];
        g_vecp[site * 32 + t] = gv;
        if (t == 0) g_c[site] = c[cell];
    }
}

// ---------------------------------------------------------------------------
// H: read left input from sHV[colprev] (prev scan site).  V: read vertical
// input from sHV[col] (prev row, not yet overwritten this row).
template <bool H, bool V>
__device__ __forceinline__ void site_body(
    const ulonglong2* __restrict__ gm,
    float* __restrict__ sHVw,              // [WELE][8][32] lattice state
    int lane, int col, int colprev,
    float4 gv, float rc, unsigned bits,
    float& la_mine, int& nc_mine)
{
    unsigned long long acc0[WELE], acc1[WELE];
    #pragma unroll
    for (int k = 0; k < WELE; ++k) { acc0[k] = 0ull; acc1[k] = 0ull; }

    if (H || V) {
        #pragma unroll
        for (int b4 = 0; b4 < 8; ++b4) {
            const ulonglong2* gb = gm + (b4 * 4) * 32 + lane;
            ulonglong2 m0, m1, m2, m3;
            if (H) { m0 = gb[0];  m1 = gb[32]; }
            if (V) { m2 = gb[64]; m3 = gb[96]; }
            #pragma unroll
            for (int k = 0; k < WELE; ++k) {
                if (H) {
                    ulonglong2 hl = *reinterpret_cast<const ulonglong2*>(
                        sHVw + (k * 8 + colprev) * 32 + b4 * 4);
                    FFMA2(acc0[k], m0.x, hl.x);  FFMA2(acc0[k], m0.y, hl.y);
                    FFMA2(acc1[k], m1.x, hl.x);  FFMA2(acc1[k], m1.y, hl.y);
                }
                if (V) {
                    ulonglong2 hv = *reinterpret_cast<const ulonglong2*>(
                        sHVw + (k * 8 + col) * 32 + b4 * 4);
                    FFMA2(acc0[k], m2.x, hv.x);  FFMA2(acc0[k], m2.y, hv.y);
                    FFMA2(acc1[k], m3.x, hv.x);  FFMA2(acc1[k], m3.y, hv.y);
                }
            }
        }
    }

    // 32 per-lane partials: cur[4k+0]=eta2*hsel^2, +1=eta2*hoth^2,
    // +2=hsel^2, +3=w*hsel.  Keep hsel for the normalized store.
    float cur[32], hsel_r[WELE];
    #pragma unroll
    for (int k = 0; k < WELE; ++k) {
        float e0, o0, e1, o1;
        UNPACK2(e0, o0, acc0[k]);
        UNPACK2(e1, o1, acc1[k]);
        float hc0 = e0 + o0 + gv.x;
        float hc1 = e1 + o1 + gv.y;
        bool  s    = (bits >> k) & 1u;
        float hsel = s ? hc1 : hc0;
        float hoth = s ? hc0 : hc1;
        hsel_r[k]  = hsel;
        float s2 = hsel * hsel;
        cur[4 * k + 0] = gv.z * s2;
        cur[4 * k + 1] = gv.z * hoth * hoth;
        cur[4 * k + 2] = s2;
        cur[4 * k + 3] = gv.w * hsel;
    }

    // Warp multireduce: 31 SHFL + 31 FADD.  Lane t = 4k+q holds total q of
    // element k afterwards.
    #pragma unroll
    for (int off = 16; off >= 1; off >>= 1) {
        bool hi = (lane & off) != 0;
        #pragma unroll
        for (int i = 0; i < off; ++i) {
            float a = cur[i], b = cur[i + off];
            float send = hi ? a : b;
            float keep = hi ? b : a;
            cur[i] = keep + __shfl_xor_sync(0xffffffffu, send, off);
        }
    }

    float S = cur[0];
    float P = __shfl_xor_sync(0xffffffffu, S, 1);   // pair partner
    int   q = lane & 3;

    // q==0: S=QS, P=QO -> dla.   q==2: S=NR -> inv (broadcast below).
    // q==3: S=AW, P=NR -> phase sign without divide.
    if (q == 0)
        la_mine += 0.5f * (__logf(S + EPSF) - __logf(S + P + EPSF));
    if (q == 3)
        nc_mine += ((S + rc * (sqrtf(P) + EPSF)) < 0.0f) ? 1 : 0;
    float inv = __fdividef(1.0f, sqrtf(S) + EPSF);  // valid at q==2

    // Normalize + store to lattice column: inv for element k is at lane 4k+2.
    #pragma unroll
    for (int k = 0; k < WELE; ++k) {
        float ik = __shfl_sync(0xffffffffu, inv, 4 * k + 2);
        sHVw[(k * 8 + col) * 32 + lane] = hsel_r[k] * ik;
    }
}

// ---------------------------------------------------------------------------
__global__ void __launch_bounds__(TPB, 4)
mps_main_kernel(const int* __restrict__ x, float* __restrict__ out, int B)
{
    extern __shared__ float smem[];
    const int lane = threadIdx.x & 31;
    const int wid  = threadIdx.x >> 5;
    const int ebl  = wid * WELE;
    float* sHVw = smem + ebl * 8 * 32;              // [WELE][8][32]
    const long eg0 = (long)blockIdx.x * EPB + ebl;

    // 64-bit occupation mask; lane k keeps element k's mask.
    unsigned long long msk = 0ull;
    #pragma unroll
    for (int k = 0; k < WELE; ++k) {
        long e = eg0 + k;
        int v0 = 0, v1 = 0;
        if (e < B) {
            v0 = x[e * NQ + lane];
            v1 = x[e * NQ + 32 + lane];
        }
        unsigned lo = __ballot_sync(0xffffffffu, v0 != 0);
        unsigned hi = __ballot_sync(0xffffffffu, v1 != 0);
        if (lane == k) msk = (unsigned long long)lo
                           | ((unsigned long long)hi << 32);
    }

    float la_mine = 0.0f;    // valid at lanes 4k+0 (element k)
    int   nc_mine = 0;       // valid at lanes 4k+3 (element k)

    #pragma unroll 1
    for (int row = 0; row < 8; ++row) {
        #pragma unroll 1
        for (int j = 0; j < 8; ++j) {
            const int site    = row * 8 + j;
            const int col     = (row & 1) ? (7 - j) : j;
            const int colprev = (row & 1) ? (8 - j) : (j - 1);  // j>0 only

            const float4 gv = g_vecp[site * 32 + lane];
            const float  rc = g_c[site];
            const ulonglong2* gm =
                reinterpret_cast<const ulonglong2*>(g2) + site * 1024;

            unsigned bits = __ballot_sync(
                0xffffffffu, (lane < WELE) && (unsigned)(msk & 1ull));
            msk >>= 1;

            if (row == 0) {
                if (j == 0)
                    site_body<false, false>(gm, sHVw, lane, col, colprev,
                                            gv, rc, bits, la_mine, nc_mine);
                else
                    site_body<true, false>(gm, sHVw, lane, col, colprev,
                                           gv, rc, bits, la_mine, nc_mine);
            } else {
                if (j == 0)
                    site_body<false, true>(gm, sHVw, lane, col, colprev,
                                           gv, rc, bits, la_mine, nc_mine);
                else
                    site_body<true, true>(gm, sHVw, lane, col, colprev,
                                          gv, rc, bits, la_mine, nc_mine);
            }
            __syncwarp();
        }
    }

    {
        int k = lane >> 2;
        long e = eg0 + k;
        if (e < B) {
            if ((lane & 3) == 0) out[e * 2 + 0] = la_mine;
            if ((lane & 3) == 3) out[e * 2 + 1] =
                3.14159274101257324f * (float)nc_mine;
        }
    }
}

// ---------------------------------------------------------------------------
extern "C" void kernel_launch(void* const* d_in, const int* in_sizes, int n_in,
                              void* d_out, int out_size) {
    const int*   x   = (const int*)  d_in[0];
    const float* Mh  = (const float*)d_in[1];
    const float* Mv  = (const float*)d_in[2];
    const float* v   = (const float*)d_in[3];
    const float* w   = (const float*)d_in[4];
    const float* c   = (const float*)d_in[5];
    const float* eta = (const float*)d_in[6];
    float* out = (float*)d_out;

    int B = in_sizes[0] / NQ;

    repack_kernel<<<64, 1024>>>(Mh, Mv, v, w, c, eta);

    const size_t smem_bytes = (size_t)(EPB * 8 * 32) * sizeof(float);
    cudaFuncSetAttribute(mps_main_kernel,
                         cudaFuncAttributeMaxDynamicSharedMemorySize,
                         (int)smem_bytes);

    int grid = (B + EPB - 1) / EPB;
    mps_main_kernel<<<grid, TPB, smem_bytes>>>(x, out, B);
}